// round 1
// baseline (speedup 1.0000x reference)
#include <cuda_runtime.h>

// Problem-instance dimensions (fixed by the dataset).
#define NN  100000
#define HH  64
#define EE  1000000

// ---------------- scratch (device globals, no allocation) ----------------
__device__ float    g_xw[(long long)NN * HH];   // x @ W for current layer
__device__ float    g_out[(long long)NN * HH];  // aggregation accumulator
__device__ float    g_h[(long long)NN * HH];    // finalized layer output
__device__ float    g_ssrc[NN];
__device__ float    g_sdst[NN];
__device__ unsigned g_menc[NN];                 // ordered-encoded segment max
__device__ float    g_den[NN];                  // softmax denominator
__device__ int      g_flags[2];                 // [0]=edge_index is64, [1]=user/movie is64

// ---------------- helpers ----------------
__device__ __forceinline__ unsigned fenc(float f) {
    unsigned u = __float_as_uint(f);
    return (u & 0x80000000u) ? ~u : (u | 0x80000000u);
}
__device__ __forceinline__ float fdec(unsigned e) {
    unsigned u = (e & 0x80000000u) ? (e ^ 0x80000000u) : ~e;
    return __uint_as_float(u);
}
__device__ __forceinline__ float lrelu(float z) { return z > 0.f ? z : 0.2f * z; }

// Index gather that works for either int32 or int64 (values fit in 31 bits).
__device__ __forceinline__ long long gidx(const int* p, long long j, int is64) {
    return is64 ? (long long)p[2 * j] : (long long)p[j];
}

// ---------------- dtype detection ----------------
// If the buffer is int64 (little-endian, values < 2^31), every odd 32-bit
// word is 0. If int32, odd words are random node ids (P(all zero) ~ 0).
__global__ void k_detect(const int* __restrict__ p, int* flag) {
    unsigned ok = __ballot_sync(0xffffffffu, p[2 * threadIdx.x + 1] == 0);
    if (threadIdx.x == 0) *flag = (ok == 0xffffffffu) ? 1 : 0;
}

// ---------------- GEMM: Y[N,64] = X[N,K] @ W[K,64] ----------------
// BM=64, BN=64(=HH), BK=16, 256 threads, 4x4 register tile per thread.
__global__ void k_gemm(const float* __restrict__ X, const float* __restrict__ W,
                       float* __restrict__ Y, int N, int K) {
    const int BM = 64, BK = 16;
    __shared__ float As[BK][BM + 1];
    __shared__ float Bs[BK][HH];
    int row0 = blockIdx.x * BM;
    int tid = threadIdx.x;
    int tr = tid >> 4;   // 0..15
    int tc = tid & 15;   // 0..15
    float acc[4][4] = {};
    for (int k0 = 0; k0 < K; k0 += BK) {
        // A tile: BM x BK
        for (int i = tid; i < BM * BK; i += 256) {
            int r = i >> 4, c = i & 15;
            int gr = row0 + r;
            As[c][r] = (gr < N) ? X[(long long)gr * K + k0 + c] : 0.f;
        }
        // B tile: BK x 64
        for (int i = tid; i < BK * HH; i += 256) {
            int r = i >> 6, c = i & 63;
            Bs[r][c] = W[(long long)(k0 + r) * HH + c];
        }
        __syncthreads();
#pragma unroll
        for (int kk = 0; kk < BK; kk++) {
            float a[4], b[4];
#pragma unroll
            for (int i = 0; i < 4; i++) a[i] = As[kk][tr * 4 + i];
#pragma unroll
            for (int j = 0; j < 4; j++) b[j] = Bs[kk][tc * 4 + j];
#pragma unroll
            for (int i = 0; i < 4; i++)
#pragma unroll
                for (int j = 0; j < 4; j++) acc[i][j] += a[i] * b[j];
        }
        __syncthreads();
    }
#pragma unroll
    for (int i = 0; i < 4; i++) {
        int gr = row0 + tr * 4 + i;
        if (gr < N) {
#pragma unroll
            for (int j = 0; j < 4; j++)
                Y[(long long)gr * HH + tc * 4 + j] = acc[i][j];
        }
    }
}

// ---------------- per-node attention logits: s = xw . a ----------------
__global__ void k_logits(const float* __restrict__ xw, const float* __restrict__ asrc,
                         const float* __restrict__ adst, float* __restrict__ ss,
                         float* __restrict__ sd, int N) {
    int warp = (blockIdx.x * blockDim.x + threadIdx.x) >> 5;
    int lane = threadIdx.x & 31;
    if (warp >= N) return;
    long long base = (long long)warp * HH;
    float v0 = xw[base + lane], v1 = xw[base + 32 + lane];
    float s1 = v0 * asrc[lane] + v1 * asrc[32 + lane];
    float s2 = v0 * adst[lane] + v1 * adst[32 + lane];
#pragma unroll
    for (int o = 16; o; o >>= 1) {
        s1 += __shfl_xor_sync(0xffffffffu, s1, o);
        s2 += __shfl_xor_sync(0xffffffffu, s2, o);
    }
    if (lane == 0) { ss[warp] = s1; sd[warp] = s2; }
}

// ---------------- init m with the self-loop logit ----------------
__global__ void k_initm(const float* __restrict__ ss, const float* __restrict__ sd,
                        unsigned* __restrict__ m, int N) {
    int i = blockIdx.x * blockDim.x + threadIdx.x;
    if (i >= N) return;
    m[i] = fenc(lrelu(ss[i] + sd[i]));
}

// ---------------- edge pass: segment max ----------------
__global__ void k_emax(const int* __restrict__ eidx, long long E,
                       const float* __restrict__ ss, const float* __restrict__ sd,
                       unsigned* __restrict__ m, const int* __restrict__ flag) {
    long long j = (long long)blockIdx.x * blockDim.x + threadIdx.x;
    if (j >= E) return;
    int is64 = *flag;
    long long s = gidx(eidx, j, is64);
    const int* dbase = eidx + (is64 ? 2 * E : E);
    long long d = gidx(dbase, j, is64);
    float e = lrelu(ss[s] + sd[d]);
    atomicMax(m + d, fenc(e));
}

// ---------------- init denom with self-loop term ----------------
__global__ void k_initd(const float* __restrict__ ss, const float* __restrict__ sd,
                        const unsigned* __restrict__ m, float* __restrict__ den, int N) {
    int i = blockIdx.x * blockDim.x + threadIdx.x;
    if (i >= N) return;
    den[i] = __expf(lrelu(ss[i] + sd[i]) - fdec(m[i]));
}

// ---------------- edge pass: segment sum of exp ----------------
__global__ void k_esum(const int* __restrict__ eidx, long long E,
                       const float* __restrict__ ss, const float* __restrict__ sd,
                       const unsigned* __restrict__ m, float* __restrict__ den,
                       const int* __restrict__ flag) {
    long long j = (long long)blockIdx.x * blockDim.x + threadIdx.x;
    if (j >= E) return;
    int is64 = *flag;
    long long s = gidx(eidx, j, is64);
    const int* dbase = eidx + (is64 ? 2 * E : E);
    long long d = gidx(dbase, j, is64);
    float e = lrelu(ss[s] + sd[d]);
    atomicAdd(den + d, __expf(e - fdec(m[d])));
}

// ---------------- init output with self-loop contribution ----------------
__global__ void k_initout(const float* __restrict__ ss, const float* __restrict__ sd,
                          const unsigned* __restrict__ m, const float* __restrict__ den,
                          const float* __restrict__ xw, float* __restrict__ out,
                          long long total) {
    long long t = (long long)blockIdx.x * blockDim.x + threadIdx.x;
    if (t >= total) return;
    int i = (int)(t >> 6);
    float a = __expf(lrelu(ss[i] + sd[i]) - fdec(m[i])) / den[i];
    out[t] = a * xw[t];
}

// ---------------- edge pass: weighted aggregation (warp per edge) ----------------
__global__ void k_eagg(const int* __restrict__ eidx, long long E,
                       const float* __restrict__ ss, const float* __restrict__ sd,
                       const unsigned* __restrict__ m, const float* __restrict__ den,
                       const float* __restrict__ xw, float* __restrict__ out,
                       const int* __restrict__ flag) {
    long long g = (long long)blockIdx.x * blockDim.x + threadIdx.x;
    long long j = g >> 5;
    int lane = threadIdx.x & 31;
    if (j >= E) return;
    int is64 = *flag;
    long long s = 0, d = 0;
    float alpha = 0.f;
    if (lane == 0) {
        s = gidx(eidx, j, is64);
        const int* dbase = eidx + (is64 ? 2 * E : E);
        d = gidx(dbase, j, is64);
        float e = lrelu(ss[s] + sd[d]);
        alpha = __expf(e - fdec(m[d])) / den[d];
    }
    s = __shfl_sync(0xffffffffu, s, 0);
    d = __shfl_sync(0xffffffffu, d, 0);
    alpha = __shfl_sync(0xffffffffu, alpha, 0);
    float2 v = *(const float2*)(xw + s * HH + lane * 2);
    atomicAdd(out + d * HH + lane * 2, alpha * v.x);
    atomicAdd(out + d * HH + lane * 2 + 1, alpha * v.y);
}

// ---------------- finalize: h = (out + b), optional relu ----------------
__global__ void k_final(const float* __restrict__ out, const float* __restrict__ b,
                        float* __restrict__ h, long long total, int do_relu) {
    long long t = (long long)blockIdx.x * blockDim.x + threadIdx.x;
    if (t >= total) return;
    float v = out[t] + b[t & 63];
    if (do_relu) v = fmaxf(v, 0.f);
    h[t] = v;
}

// ---------------- final FC over (user, movie) pairs ----------------
__global__ void k_pred(const float* __restrict__ h, const int* __restrict__ ui,
                       const int* __restrict__ mi, const float* __restrict__ fcW,
                       const float* __restrict__ fcb, float* __restrict__ out,
                       int B, const int* __restrict__ flag) {
    int warp = (blockIdx.x * blockDim.x + threadIdx.x) >> 5;
    int lane = threadIdx.x & 31;
    if (warp >= B) return;
    int is64 = *flag;
    long long u = gidx(ui, warp, is64);
    long long mv = gidx(mi, warp, is64);
    float acc = h[u * HH + lane] * fcW[lane] + h[u * HH + 32 + lane] * fcW[32 + lane] +
                h[mv * HH + lane] * fcW[64 + lane] + h[mv * HH + 32 + lane] * fcW[96 + lane];
#pragma unroll
    for (int o = 16; o; o >>= 1) acc += __shfl_xor_sync(0xffffffffu, acc, o);
    if (lane == 0) out[warp] = acc + fcb[0];
}

// ---------------- host-side layer driver ----------------
static void run_layer(const float* xin, int K, const float* W, const float* as,
                      const float* ad, const float* b, int relu,
                      int N, long long E, const int* eidx,
                      float* xw, float* out, float* h,
                      float* ss, float* sd, unsigned* menc, float* den,
                      const int* eflag) {
    long long totF = (long long)N * HH;
    k_gemm<<<(N + 63) / 64, 256>>>(xin, W, xw, N, K);
    k_logits<<<(int)(((long long)N * 32 + 255) / 256), 256>>>(xw, as, ad, ss, sd, N);
    k_initm<<<(N + 255) / 256, 256>>>(ss, sd, menc, N);
    k_emax<<<(int)((E + 255) / 256), 256>>>(eidx, E, ss, sd, menc, eflag);
    k_initd<<<(N + 255) / 256, 256>>>(ss, sd, menc, den, N);
    k_esum<<<(int)((E + 255) / 256), 256>>>(eidx, E, ss, sd, menc, den, eflag);
    k_initout<<<(int)((totF + 255) / 256), 256>>>(ss, sd, menc, den, xw, out, totF);
    k_eagg<<<(int)((E * 32 + 255) / 256), 256>>>(eidx, E, ss, sd, menc, den, xw, out, eflag);
    k_final<<<(int)((totF + 255) / 256), 256>>>(out, b, h, totF, relu);
}

extern "C" void kernel_launch(void* const* d_in, const int* in_sizes, int n_in,
                              void* d_out, int out_size) {
    const float* x   = (const float*)d_in[0];
    const int*   eix = (const int*)d_in[1];
    const int*   ui  = (const int*)d_in[2];
    const int*   mi  = (const int*)d_in[3];
    const float* W1  = (const float*)d_in[4];
    const float* as1 = (const float*)d_in[5];
    const float* ad1 = (const float*)d_in[6];
    const float* b1  = (const float*)d_in[7];
    const float* W2  = (const float*)d_in[8];
    const float* as2 = (const float*)d_in[9];
    const float* ad2 = (const float*)d_in[10];
    const float* b2  = (const float*)d_in[11];
    const float* fcW = (const float*)d_in[12];
    const float* fcb = (const float*)d_in[13];

    int H = in_sizes[5];               // 64
    int FIN = in_sizes[4] / H;         // 256
    int N = in_sizes[0] / FIN;         // 100000
    long long E = in_sizes[1] / 2;     // 1000000
    int B = in_sizes[2];               // 16384
    (void)H; (void)n_in; (void)out_size;

    float *xw, *out, *h, *ss, *sd, *den;
    unsigned* menc;
    int* flags;
    cudaGetSymbolAddress((void**)&xw, g_xw);
    cudaGetSymbolAddress((void**)&out, g_out);
    cudaGetSymbolAddress((void**)&h, g_h);
    cudaGetSymbolAddress((void**)&ss, g_ssrc);
    cudaGetSymbolAddress((void**)&sd, g_sdst);
    cudaGetSymbolAddress((void**)&menc, g_menc);
    cudaGetSymbolAddress((void**)&den, g_den);
    cudaGetSymbolAddress((void**)&flags, g_flags);

    k_detect<<<1, 32>>>(eix, flags + 0);
    k_detect<<<1, 32>>>(ui, flags + 1);

    // Layer 1: x[N,256] -> h[N,64] with ReLU
    run_layer(x, FIN, W1, as1, ad1, b1, 1, N, E, eix,
              xw, out, h, ss, sd, menc, den, flags + 0);
    // Layer 2: h[N,64] -> h[N,64] (no ReLU)
    run_layer(h, 64, W2, as2, ad2, b2, 0, N, E, eix,
              xw, out, h, ss, sd, menc, den, flags + 0);

    k_pred<<<(int)(((long long)B * 32 + 255) / 256), 256>>>(
        h, ui, mi, fcW, fcb, (float*)d_out, B, flags + 1);
}

// round 2
// speedup vs baseline: 1.6691x; 1.6691x over previous
#include <cuda_runtime.h>

#define NN  100000
#define HH  64
#define EE  1000000

// ---------------- scratch (device globals, no allocation) ----------------
__device__ __align__(16) float    g_xw[(long long)NN * HH];   // x @ W (current layer)
__device__ __align__(16) float    g_out[(long long)NN * HH];  // layer-1 aggregation acc
__device__ __align__(16) float    g_h[(long long)NN * HH];    // layer-2 aggregation acc
__device__ float    g_ssrc[NN];
__device__ float    g_sdst[NN];
__device__ unsigned g_menc[NN];                 // ordered-encoded segment max
__device__ float    g_den[NN];                  // softmax denominator
__device__ int      g_src[EE];
__device__ int      g_dst[EE];
__device__ int      g_flags[2];                 // [0]=edge_index is64, [1]=user/movie is64

// ---------------- helpers ----------------
__device__ __forceinline__ unsigned fenc(float f) {
    unsigned u = __float_as_uint(f);
    return (u & 0x80000000u) ? ~u : (u | 0x80000000u);
}
__device__ __forceinline__ float fdec(unsigned e) {
    unsigned u = (e & 0x80000000u) ? (e ^ 0x80000000u) : ~e;
    return __uint_as_float(u);
}
__device__ __forceinline__ float lrelu(float z) { return z > 0.f ? z : 0.2f * z; }

__device__ __forceinline__ void red_add_v4(float* addr, float4 v) {
    asm volatile("red.global.add.v4.f32 [%0], {%1, %2, %3, %4};"
                 :: "l"(addr), "f"(v.x), "f"(v.y), "f"(v.z), "f"(v.w) : "memory");
}

// ---------------- dtype detection ----------------
__global__ void k_detect(const int* __restrict__ p, int* flag) {
    unsigned ok = __ballot_sync(0xffffffffu, p[2 * threadIdx.x + 1] == 0);
    if (threadIdx.x == 0) *flag = (ok == 0xffffffffu) ? 1 : 0;
}

// ---------------- unpack edge index (int32 or int64) to int32 src/dst ----------------
__global__ void k_unpack(const int* __restrict__ eidx, long long E,
                         int* __restrict__ src, int* __restrict__ dst,
                         const int* __restrict__ flag) {
    long long j = (long long)blockIdx.x * blockDim.x + threadIdx.x;
    if (j >= E) return;
    if (*flag) { src[j] = eidx[2 * j]; dst[j] = eidx[2 * (E + j)]; }
    else       { src[j] = eidx[j];     dst[j] = eidx[E + j]; }
}

// ---------------- GEMM + fused logits + self-loop max init ----------------
// Y[N,64] = act(X + bias) @ W ; also ss = Y.a_src, sd = Y.a_dst, menc = enc(lrelu(ss+sd))
// BM=128, BN=64, BK=16, 256 threads, 8x4 register tile.
__global__ __launch_bounds__(256) void k_gemm(
    const float* __restrict__ X, const float* __restrict__ W,
    const float* __restrict__ bias,
    const float* __restrict__ a_s, const float* __restrict__ a_d,
    float* __restrict__ Y, float* __restrict__ ss, float* __restrict__ sd,
    unsigned* __restrict__ menc, int N, int K)
{
    const int BM = 128, BK = 16;
    __shared__ float As[BK][BM + 4];
    __shared__ float Bs[BK][HH];
    int tid = threadIdx.x;
    int row0 = blockIdx.x * BM;
    int tr = tid >> 4;    // 0..15 -> rows tr*8..tr*8+7
    int tc = tid & 15;    // 0..15 -> cols tc*4..tc*4+3
    float acc[8][4] = {};
    float4 asv = *(const float4*)(a_s + tc * 4);
    float4 adv = *(const float4*)(a_d + tc * 4);

    for (int k0 = 0; k0 < K; k0 += BK) {
        // A tile: 128 rows x 16 cols = 512 float4 slots, 2 per thread
#pragma unroll
        for (int sIt = 0; sIt < 2; sIt++) {
            int slot = tid + sIt * 256;
            int r = slot >> 2, q = slot & 3;
            int gr = row0 + r;
            float4 v = make_float4(0.f, 0.f, 0.f, 0.f);
            if (gr < N) {
                v = *(const float4*)(X + (long long)gr * K + k0 + q * 4);
                if (bias) {
                    float4 b4 = *(const float4*)(bias + k0 + q * 4);
                    v.x = fmaxf(v.x + b4.x, 0.f);
                    v.y = fmaxf(v.y + b4.y, 0.f);
                    v.z = fmaxf(v.z + b4.z, 0.f);
                    v.w = fmaxf(v.w + b4.w, 0.f);
                }
            }
            As[q * 4 + 0][r] = v.x;
            As[q * 4 + 1][r] = v.y;
            As[q * 4 + 2][r] = v.z;
            As[q * 4 + 3][r] = v.w;
        }
        // B tile: 16 x 64 = 256 float4 slots, 1 per thread
        {
            int r = tid >> 4, q = tid & 15;
            *(float4*)&Bs[r][q * 4] = *(const float4*)(W + (long long)(k0 + r) * HH + q * 4);
        }
        __syncthreads();
#pragma unroll
        for (int kk = 0; kk < BK; kk++) {
            float4 a0 = *(const float4*)&As[kk][tr * 8];
            float4 a1 = *(const float4*)&As[kk][tr * 8 + 4];
            float4 bv = *(const float4*)&Bs[kk][tc * 4];
            float a[8] = {a0.x, a0.y, a0.z, a0.w, a1.x, a1.y, a1.z, a1.w};
            float b[4] = {bv.x, bv.y, bv.z, bv.w};
#pragma unroll
            for (int i = 0; i < 8; i++)
#pragma unroll
                for (int j = 0; j < 4; j++) acc[i][j] += a[i] * b[j];
        }
        __syncthreads();
    }

    // write Y + fused logits
    float psrc[8], pdst[8];
#pragma unroll
    for (int i = 0; i < 8; i++) {
        int gr = row0 + tr * 8 + i;
        if (gr < N)
            *(float4*)(Y + (long long)gr * HH + tc * 4) =
                make_float4(acc[i][0], acc[i][1], acc[i][2], acc[i][3]);
        psrc[i] = acc[i][0] * asv.x + acc[i][1] * asv.y + acc[i][2] * asv.z + acc[i][3] * asv.w;
        pdst[i] = acc[i][0] * adv.x + acc[i][1] * adv.y + acc[i][2] * adv.z + acc[i][3] * adv.w;
    }
#pragma unroll
    for (int off = 8; off; off >>= 1) {
#pragma unroll
        for (int i = 0; i < 8; i++) {
            psrc[i] += __shfl_xor_sync(0xffffffffu, psrc[i], off);
            pdst[i] += __shfl_xor_sync(0xffffffffu, pdst[i], off);
        }
    }
    if (tc == 0) {
#pragma unroll
        for (int i = 0; i < 8; i++) {
            int gr = row0 + tr * 8 + i;
            if (gr < N) {
                ss[gr] = psrc[i];
                sd[gr] = pdst[i];
                menc[gr] = fenc(lrelu(psrc[i] + pdst[i]));  // self-loop init
            }
        }
    }
}

// ---------------- edge pass: segment max ----------------
__global__ void k_emax(const int* __restrict__ src, const int* __restrict__ dst,
                       long long E, const float* __restrict__ ss,
                       const float* __restrict__ sd, unsigned* __restrict__ m) {
    long long j = (long long)blockIdx.x * blockDim.x + threadIdx.x;
    if (j >= E) return;
    int s = src[j], d = dst[j];
    atomicMax(m + d, fenc(lrelu(ss[s] + sd[d])));
}

// ---------------- init denom with self-loop term ----------------
__global__ void k_initd(const float* __restrict__ ss, const float* __restrict__ sd,
                        const unsigned* __restrict__ m, float* __restrict__ den, int N) {
    int i = blockIdx.x * blockDim.x + threadIdx.x;
    if (i >= N) return;
    den[i] = __expf(lrelu(ss[i] + sd[i]) - fdec(m[i]));
}

// ---------------- edge pass: segment sum of exp ----------------
__global__ void k_esum(const int* __restrict__ src, const int* __restrict__ dst,
                       long long E, const float* __restrict__ ss,
                       const float* __restrict__ sd, const unsigned* __restrict__ m,
                       float* __restrict__ den) {
    long long j = (long long)blockIdx.x * blockDim.x + threadIdx.x;
    if (j >= E) return;
    int s = src[j], d = dst[j];
    atomicAdd(den + d, __expf(lrelu(ss[s] + sd[d]) - fdec(m[d])));
}

// ---------------- init output with self-loop contribution (float4) ----------------
__global__ void k_initout(const float* __restrict__ ss, const float* __restrict__ sd,
                          const unsigned* __restrict__ m, const float* __restrict__ den,
                          const float* __restrict__ xw, float* __restrict__ out,
                          long long total4) {
    long long t = (long long)blockIdx.x * blockDim.x + threadIdx.x;
    if (t >= total4) return;
    int i = (int)(t >> 4);
    float a = __expf(lrelu(ss[i] + sd[i]) - fdec(m[i])) / den[i];
    float4 v = ((const float4*)xw)[t];
    v.x *= a; v.y *= a; v.z *= a; v.w *= a;
    ((float4*)out)[t] = v;
}

// ---------------- edge aggregation: 16 lanes/edge, vector red ----------------
__global__ void k_eagg(const int* __restrict__ src, const int* __restrict__ dst,
                       long long E, const float* __restrict__ ss,
                       const float* __restrict__ sd, const unsigned* __restrict__ m,
                       const float* __restrict__ den, const float* __restrict__ xw,
                       float* __restrict__ out) {
    int lane = threadIdx.x & 31;
    long long w = ((long long)blockIdx.x * blockDim.x + threadIdx.x) >> 5;
    int sub = lane >> 4;        // half-warp id
    int l = lane & 15;          // lane within half
    long long j = w * 2 + sub;
    int s = 0, d = 0;
    float alpha = 0.f;
    if (j < E && l == 0) {
        s = src[j]; d = dst[j];
        alpha = __expf(lrelu(ss[s] + sd[d]) - fdec(m[d])) / den[d];
    }
    int leader = sub * 16;
    s = __shfl_sync(0xffffffffu, s, leader);
    d = __shfl_sync(0xffffffffu, d, leader);
    alpha = __shfl_sync(0xffffffffu, alpha, leader);
    if (j >= E) return;
    float4 v = *(const float4*)(xw + (long long)s * HH + l * 4);
    v.x *= alpha; v.y *= alpha; v.z *= alpha; v.w *= alpha;
    red_add_v4(out + (long long)d * HH + l * 4, v);
}

// ---------------- final FC over (user, movie) pairs, fused +b2 ----------------
__global__ void k_pred(const float* __restrict__ h, const float* __restrict__ b2,
                       const int* __restrict__ ui, const int* __restrict__ mi,
                       const float* __restrict__ fcW, const float* __restrict__ fcb,
                       float* __restrict__ out, int B, const int* __restrict__ flag) {
    int warp = (blockIdx.x * blockDim.x + threadIdx.x) >> 5;
    int lane = threadIdx.x & 31;
    if (warp >= B) return;
    int is64 = *flag;
    long long u  = is64 ? (long long)ui[2 * warp] : (long long)ui[warp];
    long long mv = is64 ? (long long)mi[2 * warp] : (long long)mi[warp];
    float b2l = b2[lane], b2h = b2[lane + 32];
    float acc = (h[u * HH + lane] + b2l) * fcW[lane] +
                (h[u * HH + 32 + lane] + b2h) * fcW[32 + lane] +
                (h[mv * HH + lane] + b2l) * fcW[64 + lane] +
                (h[mv * HH + 32 + lane] + b2h) * fcW[96 + lane];
#pragma unroll
    for (int o = 16; o; o >>= 1) acc += __shfl_xor_sync(0xffffffffu, acc, o);
    if (lane == 0) out[warp] = acc + fcb[0];
}

// ---------------- host-side layer driver ----------------
static void run_layer(const float* xin, int K, const float* W, const float* bias_in,
                      const float* as, const float* ad,
                      int N, long long E,
                      float* xw, float* acc,
                      float* ss, float* sd, unsigned* menc, float* den,
                      const int* src, const int* dst) {
    long long tot4 = (long long)N * (HH / 4);
    k_gemm<<<(N + 127) / 128, 256>>>(xin, W, bias_in, as, ad, xw, ss, sd, menc, N, K);
    k_emax<<<(int)((E + 255) / 256), 256>>>(src, dst, E, ss, sd, menc);
    k_initd<<<(N + 255) / 256, 256>>>(ss, sd, menc, den, N);
    k_esum<<<(int)((E + 255) / 256), 256>>>(src, dst, E, ss, sd, menc, den);
    k_initout<<<(int)((tot4 + 255) / 256), 256>>>(ss, sd, menc, den, xw, acc, tot4);
    k_eagg<<<(int)((E * 16 + 255) / 256), 256>>>(src, dst, E, ss, sd, menc, den, xw, acc);
}

extern "C" void kernel_launch(void* const* d_in, const int* in_sizes, int n_in,
                              void* d_out, int out_size) {
    const float* x   = (const float*)d_in[0];
    const int*   eix = (const int*)d_in[1];
    const int*   ui  = (const int*)d_in[2];
    const int*   mi  = (const int*)d_in[3];
    const float* W1  = (const float*)d_in[4];
    const float* as1 = (const float*)d_in[5];
    const float* ad1 = (const float*)d_in[6];
    const float* b1  = (const float*)d_in[7];
    const float* W2  = (const float*)d_in[8];
    const float* as2 = (const float*)d_in[9];
    const float* ad2 = (const float*)d_in[10];
    const float* b2  = (const float*)d_in[11];
    const float* fcW = (const float*)d_in[12];
    const float* fcb = (const float*)d_in[13];

    int H = in_sizes[5];               // 64
    int FIN = in_sizes[4] / H;         // 256
    int N = in_sizes[0] / FIN;         // 100000
    long long E = in_sizes[1] / 2;     // 1000000
    int B = in_sizes[2];               // 16384
    (void)n_in; (void)out_size;

    float *xw, *acc1, *acc2, *ss, *sd, *den;
    unsigned* menc;
    int *src, *dst, *flags;
    cudaGetSymbolAddress((void**)&xw, g_xw);
    cudaGetSymbolAddress((void**)&acc1, g_out);
    cudaGetSymbolAddress((void**)&acc2, g_h);
    cudaGetSymbolAddress((void**)&ss, g_ssrc);
    cudaGetSymbolAddress((void**)&sd, g_sdst);
    cudaGetSymbolAddress((void**)&menc, g_menc);
    cudaGetSymbolAddress((void**)&den, g_den);
    cudaGetSymbolAddress((void**)&src, g_src);
    cudaGetSymbolAddress((void**)&dst, g_dst);
    cudaGetSymbolAddress((void**)&flags, g_flags);

    k_detect<<<1, 32>>>(eix, flags + 0);
    k_detect<<<1, 32>>>(ui, flags + 1);
    k_unpack<<<(int)((E + 255) / 256), 256>>>(eix, E, src, dst, flags + 0);

    // Layer 1: x[N,256] -> acc1 (no bias applied yet; consumer applies b1+relu)
    run_layer(x, FIN, W1, nullptr, as1, ad1, N, E, xw, acc1, ss, sd, menc, den, src, dst);
    // Layer 2: act(acc1+b1)[N,64] -> acc2
    run_layer(acc1, H, W2, b1, as2, ad2, N, E, xw, acc2, ss, sd, menc, den, src, dst);

    k_pred<<<(int)(((long long)B * 32 + 255) / 256), 256>>>(
        acc2, b2, ui, mi, fcW, fcb, (float*)d_out, B, flags + 1);
}

// round 3
// speedup vs baseline: 2.3706x; 1.4203x over previous
#include <cuda_runtime.h>

#define NN  100000
#define HH  64
#define EE  1000000
#define SCAN_B 1024
#define MAXBLK 128   // >= ceil(NN/SCAN_B)=98

// ---------------- scratch (device globals, no allocation) ----------------
__device__ __align__(16) float g_xw[(long long)NN * HH];   // x @ W (current layer)
__device__ __align__(16) float g_out[(long long)NN * HH];  // layer-1 output
__device__ __align__(16) float g_h[(long long)NN * HH];    // layer-2 output
__device__ float g_ssrc[NN];
__device__ float g_sdst[NN];
__device__ int   g_src[EE];
__device__ int   g_dst[EE];
__device__ int   g_deg[NN];
__device__ int   g_off[NN + 1];
__device__ int   g_cur[NN];
__device__ int   g_csrc[EE];
__device__ int   g_part[MAXBLK];
__device__ int   g_flags[2];

typedef unsigned long long u64;

// ---------------- helpers ----------------
__device__ __forceinline__ float lrelu(float z) { return z > 0.f ? z : 0.2f * z; }

__device__ __forceinline__ u64 fma2(u64 a, u64 b, u64 c) {
    u64 d;
    asm("fma.rn.f32x2 %0, %1, %2, %3;" : "=l"(d) : "l"(a), "l"(b), "l"(c));
    return d;
}
__device__ __forceinline__ u64 pack2(float x, float y) {
    u64 d;
    asm("mov.b64 %0, {%1, %2};" : "=l"(d) : "f"(x), "f"(y));
    return d;
}
__device__ __forceinline__ void unpack2(u64 v, float& x, float& y) {
    asm("mov.b64 {%0, %1}, %2;" : "=f"(x), "=f"(y) : "l"(v));
}

// ---------------- dtype detection ----------------
__global__ void k_detect(const int* __restrict__ p, int* flag) {
    unsigned ok = __ballot_sync(0xffffffffu, p[2 * threadIdx.x + 1] == 0);
    if (threadIdx.x == 0) *flag = (ok == 0xffffffffu) ? 1 : 0;
}

// ---------------- unpack edge index + zero degree ----------------
__global__ void k_unpack(const int* __restrict__ eidx, long long E,
                         int* __restrict__ src, int* __restrict__ dst,
                         int* __restrict__ deg, int N, const int* __restrict__ flag) {
    long long j = (long long)blockIdx.x * blockDim.x + threadIdx.x;
    if (j < N) deg[j] = 0;
    if (j >= E) return;
    if (*flag) { src[j] = eidx[2 * j]; dst[j] = eidx[2 * (E + j)]; }
    else       { src[j] = eidx[j];     dst[j] = eidx[E + j]; }
}

__global__ void k_hist(const int* __restrict__ dst, long long E, int* __restrict__ deg) {
    long long j = (long long)blockIdx.x * blockDim.x + threadIdx.x;
    if (j >= E) return;
    atomicAdd(deg + dst[j], 1);
}

// ---------------- scan (3-kernel exclusive prefix sum over deg) ----------------
__global__ void k_scan1(const int* __restrict__ deg, int* __restrict__ off,
                        int* __restrict__ part, int N) {
    __shared__ int sh[SCAN_B];
    int tid = threadIdx.x;
    int i = blockIdx.x * SCAN_B + tid;
    int v = (i < N) ? deg[i] : 0;
    sh[tid] = v;
    __syncthreads();
#pragma unroll
    for (int o = 1; o < SCAN_B; o <<= 1) {
        int t = (tid >= o) ? sh[tid - o] : 0;
        __syncthreads();
        sh[tid] += t;
        __syncthreads();
    }
    if (i < N) off[i] = sh[tid] - v;           // exclusive within block
    if (tid == SCAN_B - 1) part[blockIdx.x] = sh[tid];
}

__global__ void k_scan2(int* __restrict__ part, int nblocks) {
    if (threadIdx.x == 0) {
        int run = 0;
        for (int b = 0; b < nblocks; b++) {
            int v = part[b];
            part[b] = run;
            run += v;
        }
    }
}

__global__ void k_scan3(int* __restrict__ off, const int* __restrict__ part,
                        int* __restrict__ cur, int N, int Etot) {
    int i = blockIdx.x * blockDim.x + threadIdx.x;
    if (i == 0) off[N] = Etot;
    if (i >= N) return;
    int o = off[i] + part[i / SCAN_B];
    off[i] = o;
    cur[i] = o;
}

__global__ void k_scatter(const int* __restrict__ src, const int* __restrict__ dst,
                          long long E, int* __restrict__ cur, int* __restrict__ csrc) {
    long long j = (long long)blockIdx.x * blockDim.x + threadIdx.x;
    if (j >= E) return;
    int p = atomicAdd(cur + dst[j], 1);
    csrc[p] = src[j];
}

// ---------------- GEMM (f32x2 packed) + fused logits ----------------
// Y[N,64] = act(X + bias) @ W ; ss = Y.a_src ; sd = Y.a_dst
// BM=128, BN=64, BK=16, 256 threads, 8x4 register tile (packed row-pairs).
__global__ __launch_bounds__(256) void k_gemm(
    const float* __restrict__ X, const float* __restrict__ W,
    const float* __restrict__ bias,
    const float* __restrict__ a_s, const float* __restrict__ a_d,
    float* __restrict__ Y, float* __restrict__ ss, float* __restrict__ sd,
    int N, int K)
{
    const int BM = 128, BK = 16;
    __shared__ float As[BK][BM + 4];
    __shared__ float Bs[BK][HH];
    int tid = threadIdx.x;
    int row0 = blockIdx.x * BM;
    int tr = tid >> 4;    // 0..15 -> rows tr*8..tr*8+7
    int tc = tid & 15;    // 0..15 -> cols tc*4..tc*4+3
    u64 accp[4][4];       // [row-pair][col] ; lo = even local row
#pragma unroll
    for (int i = 0; i < 4; i++)
#pragma unroll
        for (int j = 0; j < 4; j++) accp[i][j] = 0ull;
    float4 asv = *(const float4*)(a_s + tc * 4);
    float4 adv = *(const float4*)(a_d + tc * 4);

    for (int k0 = 0; k0 < K; k0 += BK) {
#pragma unroll
        for (int sIt = 0; sIt < 2; sIt++) {
            int slot = tid + sIt * 256;
            int r = slot >> 2, q = slot & 3;
            int gr = row0 + r;
            float4 v = make_float4(0.f, 0.f, 0.f, 0.f);
            if (gr < N) {
                v = *(const float4*)(X + (long long)gr * K + k0 + q * 4);
                if (bias) {
                    float4 b4 = *(const float4*)(bias + k0 + q * 4);
                    v.x = fmaxf(v.x + b4.x, 0.f);
                    v.y = fmaxf(v.y + b4.y, 0.f);
                    v.z = fmaxf(v.z + b4.z, 0.f);
                    v.w = fmaxf(v.w + b4.w, 0.f);
                }
            }
            As[q * 4 + 0][r] = v.x;
            As[q * 4 + 1][r] = v.y;
            As[q * 4 + 2][r] = v.z;
            As[q * 4 + 3][r] = v.w;
        }
        {
            int r = tid >> 4, q = tid & 15;
            *(float4*)&Bs[r][q * 4] = *(const float4*)(W + (long long)(k0 + r) * HH + q * 4);
        }
        __syncthreads();
#pragma unroll
        for (int kk = 0; kk < BK; kk++) {
            float4 a0 = *(const float4*)&As[kk][tr * 8];
            float4 a1 = *(const float4*)&As[kk][tr * 8 + 4];
            float4 bv = *(const float4*)&Bs[kk][tc * 4];
            u64 ap[4];
            ap[0] = pack2(a0.x, a0.y);
            ap[1] = pack2(a0.z, a0.w);
            ap[2] = pack2(a1.x, a1.y);
            ap[3] = pack2(a1.z, a1.w);
            u64 bb[4];
            bb[0] = pack2(bv.x, bv.x);
            bb[1] = pack2(bv.y, bv.y);
            bb[2] = pack2(bv.z, bv.z);
            bb[3] = pack2(bv.w, bv.w);
#pragma unroll
            for (int i = 0; i < 4; i++)
#pragma unroll
                for (int j = 0; j < 4; j++)
                    accp[i][j] = fma2(ap[i], bb[j], accp[i][j]);
        }
        __syncthreads();
    }

    // unpack accumulators
    float acc[8][4];
#pragma unroll
    for (int i = 0; i < 4; i++)
#pragma unroll
        for (int j = 0; j < 4; j++)
            unpack2(accp[i][j], acc[2 * i][j], acc[2 * i + 1][j]);

    // write Y + fused logits
    float psrc[8], pdst[8];
#pragma unroll
    for (int i = 0; i < 8; i++) {
        int gr = row0 + tr * 8 + i;
        if (gr < N)
            *(float4*)(Y + (long long)gr * HH + tc * 4) =
                make_float4(acc[i][0], acc[i][1], acc[i][2], acc[i][3]);
        psrc[i] = acc[i][0] * asv.x + acc[i][1] * asv.y + acc[i][2] * asv.z + acc[i][3] * asv.w;
        pdst[i] = acc[i][0] * adv.x + acc[i][1] * adv.y + acc[i][2] * adv.z + acc[i][3] * adv.w;
    }
#pragma unroll
    for (int off = 8; off; off >>= 1) {
#pragma unroll
        for (int i = 0; i < 8; i++) {
            psrc[i] += __shfl_xor_sync(0xffffffffu, psrc[i], off);
            pdst[i] += __shfl_xor_sync(0xffffffffu, pdst[i], off);
        }
    }
    if (tc == 0) {
#pragma unroll
        for (int i = 0; i < 8; i++) {
            int gr = row0 + tr * 8 + i;
            if (gr < N) { ss[gr] = psrc[i]; sd[gr] = pdst[i]; }
        }
    }
}

// ---------------- fused per-node softmax + aggregation (warp per dst node) ----------------
__global__ __launch_bounds__(256) void k_nodeagg(
    const int* __restrict__ off, const int* __restrict__ csrc,
    const float* __restrict__ ss, const float* __restrict__ sd,
    const float* __restrict__ xw, float* __restrict__ out, int N)
{
    int warp = (blockIdx.x * blockDim.x + threadIdx.x) >> 5;
    int lane = threadIdx.x & 31;
    if (warp >= N) return;
    int beg = off[warp], end = off[warp + 1];
    float sdi = sd[warp];
    float selfe = lrelu(ss[warp] + sdi);

    // pass 1: segment max (lanes cover edges in parallel)
    float lm = selfe;
    for (int c = beg; c < end; c += 32) {
        int idx = c + lane;
        if (idx < end) lm = fmaxf(lm, lrelu(ss[csrc[idx]] + sdi));
    }
#pragma unroll
    for (int o = 16; o; o >>= 1)
        lm = fmaxf(lm, __shfl_xor_sync(0xffffffffu, lm, o));
    float mmax = lm;   // identical in all lanes

    // pass 2: exp-sum + weighted accumulate
    float lsum = __expf(selfe - mmax);
    long long mybase = (long long)warp * HH + lane * 2;
    float2 acc = *(const float2*)(xw + mybase);
    acc.x *= lsum; acc.y *= lsum;

    for (int c = beg; c < end; c += 32) {
        int idx = c + lane;
        int cnt = min(32, end - c);
        int s = 0;
        float w = 0.f;
        if (idx < end) {
            s = csrc[idx];
            w = __expf(lrelu(ss[s] + sdi) - mmax);
        }
        // warp-wide sum of w
        float ws = w;
#pragma unroll
        for (int o = 16; o; o >>= 1) ws += __shfl_xor_sync(0xffffffffu, ws, o);
        lsum += ws;
        // accumulate the cnt edges' feature rows
        for (int k = 0; k < cnt; k++) {
            float wk = __shfl_sync(0xffffffffu, w, k);
            int sk = __shfl_sync(0xffffffffu, s, k);
            float2 v = *(const float2*)(xw + (long long)sk * HH + lane * 2);
            acc.x += wk * v.x;
            acc.y += wk * v.y;
        }
    }
    float inv = 1.0f / lsum;
    acc.x *= inv; acc.y *= inv;
    *(float2*)(out + mybase) = acc;
}

// ---------------- final FC over (user, movie) pairs, fused +b2 ----------------
__global__ void k_pred(const float* __restrict__ h, const float* __restrict__ b2,
                       const int* __restrict__ ui, const int* __restrict__ mi,
                       const float* __restrict__ fcW, const float* __restrict__ fcb,
                       float* __restrict__ out, int B, const int* __restrict__ flag) {
    int warp = (blockIdx.x * blockDim.x + threadIdx.x) >> 5;
    int lane = threadIdx.x & 31;
    if (warp >= B) return;
    int is64 = *flag;
    long long u  = is64 ? (long long)ui[2 * warp] : (long long)ui[warp];
    long long mv = is64 ? (long long)mi[2 * warp] : (long long)mi[warp];
    float b2l = b2[lane], b2h = b2[lane + 32];
    float acc = (h[u * HH + lane] + b2l) * fcW[lane] +
                (h[u * HH + 32 + lane] + b2h) * fcW[32 + lane] +
                (h[mv * HH + lane] + b2l) * fcW[64 + lane] +
                (h[mv * HH + 32 + lane] + b2h) * fcW[96 + lane];
#pragma unroll
    for (int o = 16; o; o >>= 1) acc += __shfl_xor_sync(0xffffffffu, acc, o);
    if (lane == 0) out[warp] = acc + fcb[0];
}

extern "C" void kernel_launch(void* const* d_in, const int* in_sizes, int n_in,
                              void* d_out, int out_size) {
    const float* x   = (const float*)d_in[0];
    const int*   eix = (const int*)d_in[1];
    const int*   ui  = (const int*)d_in[2];
    const int*   mi  = (const int*)d_in[3];
    const float* W1  = (const float*)d_in[4];
    const float* as1 = (const float*)d_in[5];
    const float* ad1 = (const float*)d_in[6];
    const float* b1  = (const float*)d_in[7];
    const float* W2  = (const float*)d_in[8];
    const float* as2 = (const float*)d_in[9];
    const float* ad2 = (const float*)d_in[10];
    const float* b2  = (const float*)d_in[11];
    const float* fcW = (const float*)d_in[12];
    const float* fcb = (const float*)d_in[13];

    int H = in_sizes[5];               // 64
    int FIN = in_sizes[4] / H;         // 256
    int N = in_sizes[0] / FIN;         // 100000
    long long E = in_sizes[1] / 2;     // 1000000
    int B = in_sizes[2];               // 16384
    (void)n_in; (void)out_size;

    float *xw, *acc1, *acc2, *ss, *sd;
    int *src, *dst, *deg, *off, *cur, *csrc, *part, *flags;
    cudaGetSymbolAddress((void**)&xw, g_xw);
    cudaGetSymbolAddress((void**)&acc1, g_out);
    cudaGetSymbolAddress((void**)&acc2, g_h);
    cudaGetSymbolAddress((void**)&ss, g_ssrc);
    cudaGetSymbolAddress((void**)&sd, g_sdst);
    cudaGetSymbolAddress((void**)&src, g_src);
    cudaGetSymbolAddress((void**)&dst, g_dst);
    cudaGetSymbolAddress((void**)&deg, g_deg);
    cudaGetSymbolAddress((void**)&off, g_off);
    cudaGetSymbolAddress((void**)&cur, g_cur);
    cudaGetSymbolAddress((void**)&csrc, g_csrc);
    cudaGetSymbolAddress((void**)&part, g_part);
    cudaGetSymbolAddress((void**)&flags, g_flags);

    int nblocks = (N + SCAN_B - 1) / SCAN_B;

    k_detect<<<1, 32>>>(eix, flags + 0);
    k_detect<<<1, 32>>>(ui, flags + 1);
    k_unpack<<<(int)((E + 255) / 256), 256>>>(eix, E, src, dst, deg, N, flags + 0);
    k_hist<<<(int)((E + 255) / 256), 256>>>(dst, E, deg);
    k_scan1<<<nblocks, SCAN_B>>>(deg, off, part, N);
    k_scan2<<<1, 32>>>(part, nblocks);
    k_scan3<<<(N + 255) / 256, 256>>>(off, part, cur, N, (int)E);
    k_scatter<<<(int)((E + 255) / 256), 256>>>(src, dst, E, cur, csrc);

    // Layer 1: x[N,256] -> acc1 (b1+relu deferred to GEMM2's A-load)
    k_gemm<<<(N + 127) / 128, 256>>>(x, W1, nullptr, as1, ad1, xw, ss, sd, N, FIN);
    k_nodeagg<<<(int)(((long long)N * 32 + 255) / 256), 256>>>(off, csrc, ss, sd, xw, acc1, N);

    // Layer 2: act(acc1+b1)[N,64] -> acc2 (b2 deferred to k_pred)
    k_gemm<<<(N + 127) / 128, 256>>>(acc1, W2, b1, as2, ad2, xw, ss, sd, N, H);
    k_nodeagg<<<(int)(((long long)N * 32 + 255) / 256), 256>>>(off, csrc, ss, sd, xw, acc2, N);

    k_pred<<<(int)(((long long)B * 32 + 255) / 256), 256>>>(
        acc2, b2, ui, mi, fcW, fcb, (float*)d_out, B, flags + 1);
}

// round 4
// speedup vs baseline: 2.8579x; 1.2056x over previous
#include <cuda_runtime.h>

#define NN  100000
#define HH  64
#define EE  1000000
#define SCAN_B 1024
#define MAXBLK 128   // >= ceil(NN/SCAN_B)=98

// ---------------- scratch (device globals, no allocation) ----------------
__device__ __align__(16) float g_xw[(long long)NN * HH];   // x @ W (current layer)
__device__ __align__(16) float g_out[(long long)NN * HH];  // layer-1 output
__device__ __align__(16) float g_h[(long long)NN * HH];    // layer-2 output
__device__ float g_ssrc[NN];
__device__ float g_sdst[NN];
__device__ int   g_src[EE];
__device__ int   g_dst[EE];
__device__ int   g_deg[NN];
__device__ int   g_off[NN + 1];
__device__ int   g_cur[NN];
__device__ int   g_csrc[EE];
__device__ int   g_part[MAXBLK];
__device__ int   g_flags[2];

// ---------------- helpers ----------------
__device__ __forceinline__ float lrelu(float z) { return z > 0.f ? z : 0.2f * z; }

__device__ __forceinline__ unsigned f2tf32(float f) {
    unsigned r;
    asm("cvt.rna.tf32.f32 %0, %1;" : "=r"(r) : "f"(f));
    return r;
}

__device__ __forceinline__ void mma_tf32(float c[4], const unsigned a[4], const unsigned b[2]) {
    asm volatile(
        "mma.sync.aligned.m16n8k8.row.col.f32.tf32.tf32.f32 "
        "{%0,%1,%2,%3}, {%4,%5,%6,%7}, {%8,%9}, {%0,%1,%2,%3};"
        : "+f"(c[0]), "+f"(c[1]), "+f"(c[2]), "+f"(c[3])
        : "r"(a[0]), "r"(a[1]), "r"(a[2]), "r"(a[3]), "r"(b[0]), "r"(b[1]));
}

// ---------------- dtype detection ----------------
__global__ void k_detect(const int* __restrict__ p, int* flag) {
    unsigned ok = __ballot_sync(0xffffffffu, p[2 * threadIdx.x + 1] == 0);
    if (threadIdx.x == 0) *flag = (ok == 0xffffffffu) ? 1 : 0;
}

__global__ void k_zero(int* __restrict__ deg, int N) {
    int i = blockIdx.x * blockDim.x + threadIdx.x;
    if (i < N) deg[i] = 0;
}

// ---------------- unpack edge index + fused degree histogram ----------------
__global__ void k_unpack(const int* __restrict__ eidx, long long E,
                         int* __restrict__ src, int* __restrict__ dst,
                         int* __restrict__ deg, const int* __restrict__ flag) {
    long long j = (long long)blockIdx.x * blockDim.x + threadIdx.x;
    if (j >= E) return;
    int s, d;
    if (*flag) { s = eidx[2 * j]; d = eidx[2 * (E + j)]; }
    else       { s = eidx[j];     d = eidx[E + j]; }
    src[j] = s;
    dst[j] = d;
    atomicAdd(deg + d, 1);
}

// ---------------- scan (3-kernel exclusive prefix sum over deg) ----------------
__global__ void k_scan1(const int* __restrict__ deg, int* __restrict__ off,
                        int* __restrict__ part, int N) {
    __shared__ int sh[SCAN_B];
    int tid = threadIdx.x;
    int i = blockIdx.x * SCAN_B + tid;
    int v = (i < N) ? deg[i] : 0;
    sh[tid] = v;
    __syncthreads();
#pragma unroll
    for (int o = 1; o < SCAN_B; o <<= 1) {
        int t = (tid >= o) ? sh[tid - o] : 0;
        __syncthreads();
        sh[tid] += t;
        __syncthreads();
    }
    if (i < N) off[i] = sh[tid] - v;           // exclusive within block
    if (tid == SCAN_B - 1) part[blockIdx.x] = sh[tid];
}

// parallel exclusive scan of block partials (nblocks <= 128), one block
__global__ void k_scan2(int* __restrict__ part, int nblocks) {
    __shared__ int sh[128];
    int t = threadIdx.x;
    int v = (t < nblocks) ? part[t] : 0;
    sh[t] = v;
    __syncthreads();
#pragma unroll
    for (int o = 1; o < 128; o <<= 1) {
        int u = (t >= o) ? sh[t - o] : 0;
        __syncthreads();
        sh[t] += u;
        __syncthreads();
    }
    if (t < nblocks) part[t] = sh[t] - v;
}

__global__ void k_scan3(int* __restrict__ off, const int* __restrict__ part,
                        int* __restrict__ cur, int N, int Etot) {
    int i = blockIdx.x * blockDim.x + threadIdx.x;
    if (i == 0) off[N] = Etot;
    if (i >= N) return;
    int o = off[i] + part[i / SCAN_B];
    off[i] = o;
    cur[i] = o;
}

__global__ void k_scatter(const int* __restrict__ src, const int* __restrict__ dst,
                          long long E, int* __restrict__ cur, int* __restrict__ csrc) {
    long long j = (long long)blockIdx.x * blockDim.x + threadIdx.x;
    if (j >= E) return;
    int p = atomicAdd(cur + dst[j], 1);
    csrc[p] = src[j];
}

// ---------------- tf32 tensor-core GEMM + fused logits ----------------
// Y[N,64] = act(X + bias) @ W ; ss = Y.a_src ; sd = Y.a_dst
// BM=128, BN=64, BK=32; 8 warps: warpM 0..3 (M 32 each), warpN 0..1 (N 32 each).
// Per warp: 2 m-tiles (16) x 4 n-tiles (8), mma.m16n8k8.
#define A_STRIDE 136   // 128 + 8 pad: conflict-free frag loads
#define B_STRIDE 72    // 64 + 8 pad
__global__ __launch_bounds__(256) void k_gemm(
    const float* __restrict__ X, const float* __restrict__ W,
    const float* __restrict__ bias,
    const float* __restrict__ a_s, const float* __restrict__ a_d,
    float* __restrict__ Y, float* __restrict__ ss, float* __restrict__ sd,
    int N, int K)
{
    __shared__ unsigned As[32][A_STRIDE];   // [k][m], tf32 bits
    __shared__ unsigned Bs[32][B_STRIDE];   // [k][n], tf32 bits
    __shared__ float sPs[2][128], sPd[2][128];

    int tid = threadIdx.x;
    int lane = tid & 31;
    int wid = tid >> 5;
    int warpM = wid & 3;        // 0..3
    int warpN = wid >> 2;       // 0..1
    int gid = lane >> 2;        // 0..7 (group/row id)
    int tig = lane & 3;         // 0..3 (thread in group)
    int row0 = blockIdx.x * 128;

    float acc[2][4][4];         // [mt][nt][reg]
#pragma unroll
    for (int i = 0; i < 2; i++)
#pragma unroll
        for (int j = 0; j < 4; j++)
#pragma unroll
            for (int r = 0; r < 4; r++) acc[i][j][r] = 0.f;

    for (int k0 = 0; k0 < K; k0 += 32) {
        // stage A: 128 rows x 32 cols = 1024 float4 slots, 4 per thread
#pragma unroll
        for (int it = 0; it < 4; it++) {
            int slot = it * 256 + tid;
            int r = slot >> 3, q = slot & 7;
            int gr = row0 + r;
            float4 v = make_float4(0.f, 0.f, 0.f, 0.f);
            if (gr < N) {
                v = *(const float4*)(X + (long long)gr * K + k0 + q * 4);
                if (bias) {
                    float4 b4 = *(const float4*)(bias + k0 + q * 4);
                    v.x = fmaxf(v.x + b4.x, 0.f);
                    v.y = fmaxf(v.y + b4.y, 0.f);
                    v.z = fmaxf(v.z + b4.z, 0.f);
                    v.w = fmaxf(v.w + b4.w, 0.f);
                }
            }
            As[q * 4 + 0][r] = f2tf32(v.x);
            As[q * 4 + 1][r] = f2tf32(v.y);
            As[q * 4 + 2][r] = f2tf32(v.z);
            As[q * 4 + 3][r] = f2tf32(v.w);
        }
        // stage B: 32 x 64 = 512 float4 slots, 2 per thread
#pragma unroll
        for (int it = 0; it < 2; it++) {
            int slot = it * 256 + tid;
            int r = slot >> 4, q = slot & 15;
            float4 v = *(const float4*)(W + (long long)(k0 + r) * HH + q * 4);
            Bs[r][q * 4 + 0] = f2tf32(v.x);
            Bs[r][q * 4 + 1] = f2tf32(v.y);
            Bs[r][q * 4 + 2] = f2tf32(v.z);
            Bs[r][q * 4 + 3] = f2tf32(v.w);
        }
        __syncthreads();

#pragma unroll
        for (int ks = 0; ks < 32; ks += 8) {
            unsigned a[2][4], b[4][2];
#pragma unroll
            for (int mt = 0; mt < 2; mt++) {
                int m = warpM * 32 + mt * 16 + gid;
                a[mt][0] = As[ks + tig][m];
                a[mt][1] = As[ks + tig][m + 8];
                a[mt][2] = As[ks + tig + 4][m];
                a[mt][3] = As[ks + tig + 4][m + 8];
            }
#pragma unroll
            for (int nt = 0; nt < 4; nt++) {
                int n = warpN * 32 + nt * 8 + gid;
                b[nt][0] = Bs[ks + tig][n];
                b[nt][1] = Bs[ks + tig + 4][n];
            }
#pragma unroll
            for (int mt = 0; mt < 2; mt++)
#pragma unroll
                for (int nt = 0; nt < 4; nt++)
                    mma_tf32(acc[mt][nt], a[mt], b[nt]);
        }
        __syncthreads();
    }

    // ---- epilogue: store Y + fused logits ----
    // attention-vector values for this thread's 8 columns (per nt: tig*2, tig*2+1)
    float av_s[4][2], av_d[4][2];
#pragma unroll
    for (int nt = 0; nt < 4; nt++) {
        int c = warpN * 32 + nt * 8 + tig * 2;
        av_s[nt][0] = a_s[c];     av_s[nt][1] = a_s[c + 1];
        av_d[nt][0] = a_d[c];     av_d[nt][1] = a_d[c + 1];
    }

#pragma unroll
    for (int mt = 0; mt < 2; mt++) {
#pragma unroll
        for (int half = 0; half < 2; half++) {
            int lr = warpM * 32 + mt * 16 + half * 8 + gid;   // local row 0..127
            int gr = row0 + lr;
            float ps = 0.f, pd = 0.f;
#pragma unroll
            for (int nt = 0; nt < 4; nt++) {
                float v0 = acc[mt][nt][2 * half];
                float v1 = acc[mt][nt][2 * half + 1];
                ps += v0 * av_s[nt][0] + v1 * av_s[nt][1];
                pd += v0 * av_d[nt][0] + v1 * av_d[nt][1];
                if (gr < N) {
                    int c = warpN * 32 + nt * 8 + tig * 2;
                    *(float2*)(Y + (long long)gr * HH + c) = make_float2(v0, v1);
                }
            }
            // reduce across the 4 tig lanes
            ps += __shfl_xor_sync(0xffffffffu, ps, 1);
            ps += __shfl_xor_sync(0xffffffffu, ps, 2);
            pd += __shfl_xor_sync(0xffffffffu, pd, 1);
            pd += __shfl_xor_sync(0xffffffffu, pd, 2);
            if (tig == 0) { sPs[warpN][lr] = ps; sPd[warpN][lr] = pd; }
        }
    }
    __syncthreads();
    if (tid < 128) {
        int gr = row0 + tid;
        if (gr < N) {
            ss[gr] = sPs[0][tid] + sPs[1][tid];
            sd[gr] = sPd[0][tid] + sPd[1][tid];
        }
    }
}

// ---------------- fused per-node softmax + aggregation (warp per dst node) ----------------
__global__ __launch_bounds__(256) void k_nodeagg(
    const int* __restrict__ off, const int* __restrict__ csrc,
    const float* __restrict__ ss, const float* __restrict__ sd,
    const float* __restrict__ xw, float* __restrict__ out, int N)
{
    int warp = (blockIdx.x * blockDim.x + threadIdx.x) >> 5;
    int lane = threadIdx.x & 31;
    if (warp >= N) return;
    int beg = off[warp], end = off[warp + 1];
    float sdi = sd[warp];
    float selfe = lrelu(ss[warp] + sdi);

    // pass 1: segment max
    float lm = selfe;
    for (int c = beg; c < end; c += 32) {
        int idx = c + lane;
        if (idx < end) lm = fmaxf(lm, lrelu(ss[csrc[idx]] + sdi));
    }
#pragma unroll
    for (int o = 16; o; o >>= 1)
        lm = fmaxf(lm, __shfl_xor_sync(0xffffffffu, lm, o));
    float mmax = lm;

    // pass 2: exp-sum + weighted accumulate
    float lsum = __expf(selfe - mmax);
    long long mybase = (long long)warp * HH + lane * 2;
    float2 acc = *(const float2*)(xw + mybase);
    acc.x *= lsum; acc.y *= lsum;

    for (int c = beg; c < end; c += 32) {
        int idx = c + lane;
        int cnt = min(32, end - c);
        int s = 0;
        float w = 0.f;
        if (idx < end) {
            s = csrc[idx];
            w = __expf(lrelu(ss[s] + sdi) - mmax);
        }
        float wsum = w;
#pragma unroll
        for (int o = 16; o; o >>= 1) wsum += __shfl_xor_sync(0xffffffffu, wsum, o);
        lsum += wsum;
        for (int k = 0; k < cnt; k++) {
            float wk = __shfl_sync(0xffffffffu, w, k);
            int sk = __shfl_sync(0xffffffffu, s, k);
            float2 v = *(const float2*)(xw + (long long)sk * HH + lane * 2);
            acc.x += wk * v.x;
            acc.y += wk * v.y;
        }
    }
    float inv = 1.0f / lsum;
    acc.x *= inv; acc.y *= inv;
    *(float2*)(out + mybase) = acc;
}

// ---------------- final FC over (user, movie) pairs, fused +b2 ----------------
__global__ void k_pred(const float* __restrict__ h, const float* __restrict__ b2,
                       const int* __restrict__ ui, const int* __restrict__ mi,
                       const float* __restrict__ fcW, const float* __restrict__ fcb,
                       float* __restrict__ out, int B, const int* __restrict__ flag) {
    int warp = (blockIdx.x * blockDim.x + threadIdx.x) >> 5;
    int lane = threadIdx.x & 31;
    if (warp >= B) return;
    int is64 = *flag;
    long long u  = is64 ? (long long)ui[2 * warp] : (long long)ui[warp];
    long long mv = is64 ? (long long)mi[2 * warp] : (long long)mi[warp];
    float b2l = b2[lane], b2h = b2[lane + 32];
    float acc = (h[u * HH + lane] + b2l) * fcW[lane] +
                (h[u * HH + 32 + lane] + b2h) * fcW[32 + lane] +
                (h[mv * HH + lane] + b2l) * fcW[64 + lane] +
                (h[mv * HH + 32 + lane] + b2h) * fcW[96 + lane];
#pragma unroll
    for (int o = 16; o; o >>= 1) acc += __shfl_xor_sync(0xffffffffu, acc, o);
    if (lane == 0) out[warp] = acc + fcb[0];
}

extern "C" void kernel_launch(void* const* d_in, const int* in_sizes, int n_in,
                              void* d_out, int out_size) {
    const float* x   = (const float*)d_in[0];
    const int*   eix = (const int*)d_in[1];
    const int*   ui  = (const int*)d_in[2];
    const int*   mi  = (const int*)d_in[3];
    const float* W1  = (const float*)d_in[4];
    const float* as1 = (const float*)d_in[5];
    const float* ad1 = (const float*)d_in[6];
    const float* b1  = (const float*)d_in[7];
    const float* W2  = (const float*)d_in[8];
    const float* as2 = (const float*)d_in[9];
    const float* ad2 = (const float*)d_in[10];
    const float* b2  = (const float*)d_in[11];
    const float* fcW = (const float*)d_in[12];
    const float* fcb = (const float*)d_in[13];

    int H = in_sizes[5];               // 64
    int FIN = in_sizes[4] / H;         // 256
    int N = in_sizes[0] / FIN;         // 100000
    long long E = in_sizes[1] / 2;     // 1000000
    int B = in_sizes[2];               // 16384
    (void)n_in; (void)out_size;

    float *xw, *acc1, *acc2, *ss, *sd;
    int *src, *dst, *deg, *off, *cur, *csrc, *part, *flags;
    cudaGetSymbolAddress((void**)&xw, g_xw);
    cudaGetSymbolAddress((void**)&acc1, g_out);
    cudaGetSymbolAddress((void**)&acc2, g_h);
    cudaGetSymbolAddress((void**)&ss, g_ssrc);
    cudaGetSymbolAddress((void**)&sd, g_sdst);
    cudaGetSymbolAddress((void**)&src, g_src);
    cudaGetSymbolAddress((void**)&dst, g_dst);
    cudaGetSymbolAddress((void**)&deg, g_deg);
    cudaGetSymbolAddress((void**)&off, g_off);
    cudaGetSymbolAddress((void**)&cur, g_cur);
    cudaGetSymbolAddress((void**)&csrc, g_csrc);
    cudaGetSymbolAddress((void**)&part, g_part);
    cudaGetSymbolAddress((void**)&flags, g_flags);

    int nblocks = (N + SCAN_B - 1) / SCAN_B;

    k_detect<<<1, 32>>>(eix, flags + 0);
    k_detect<<<1, 32>>>(ui, flags + 1);
    k_zero<<<(N + 1023) / 1024, 1024>>>(deg, N);
    k_unpack<<<(int)((E + 255) / 256), 256>>>(eix, E, src, dst, deg, flags + 0);
    k_scan1<<<nblocks, SCAN_B>>>(deg, off, part, N);
    k_scan2<<<1, 128>>>(part, nblocks);
    k_scan3<<<(N + 255) / 256, 256>>>(off, part, cur, N, (int)E);
    k_scatter<<<(int)((E + 255) / 256), 256>>>(src, dst, E, cur, csrc);

    // Layer 1: x[N,256] -> acc1 (b1+relu deferred to GEMM2's A-load)
    k_gemm<<<(N + 127) / 128, 256>>>(x, W1, nullptr, as1, ad1, xw, ss, sd, N, FIN);
    k_nodeagg<<<(int)(((long long)N * 32 + 255) / 256), 256>>>(off, csrc, ss, sd, xw, acc1, N);

    // Layer 2: act(acc1+b1)[N,64] -> acc2 (b2 deferred to k_pred)
    k_gemm<<<(N + 127) / 128, 256>>>(acc1, W2, b1, as2, ad2, xw, ss, sd, N, H);
    k_nodeagg<<<(int)(((long long)N * 32 + 255) / 256), 256>>>(off, csrc, ss, sd, xw, acc2, N);

    k_pred<<<(int)(((long long)B * 32 + 255) / 256), 256>>>(
        acc2, b2, ui, mi, fcW, fcb, (float*)d_out, B, flags + 1);
}